// round 4
// baseline (speedup 1.0000x reference)
#include <cuda_runtime.h>
#include <cstdint>

#define BATCH 2048
#define VOCAB 50000
#define EMB   100
#define CTX   10
#define KP    128          // K padded to 128 (4 x k32 mma steps)
#define VP    50176        // 392 * 128
#define BM    128
#define BN    128
#define NTILES 392
#define NSPLIT 28
#define TPC    14          // tiles per CTA = 392/28
#define STR    144         // smem row stride in bytes (conflict-free frag loads)
#define ABYTES (BM * STR)  // 18432
#define SMEM_TOTAL (ABYTES * 3)  // A + 2 B buffers = 55296

#define QU (127.0f / 5.5f)
#define QH (127.0f / 1.6f)
#define SCALE ((5.5f / 127.0f) * (1.6f / 127.0f))

// Scratch (device globals)
__device__ float                 g_h[BATCH * EMB];
__device__ __align__(16) char    g_hq[BATCH * KP];
__device__ __align__(16) char    g_uq[VP * KP];
__device__ float                 g_negsum[BATCH];
__device__ float                 g_perb[BATCH];

__device__ __forceinline__ uint32_t s2u(const void* p) {
    uint32_t a;
    asm("{ .reg .u64 t; cvta.to.shared.u64 t, %1; cvt.u32.u64 %0, t; }" : "=r"(a) : "l"(p));
    return a;
}
__device__ __forceinline__ float tanh_approx(float x) {
    float y;
    asm("tanh.approx.f32 %0, %1;" : "=f"(y) : "f"(x));
    return y;
}
__device__ __forceinline__ void cpa16(uint32_t dst, const void* src) {
    asm volatile("cp.async.cg.shared.global [%0], [%1], 16;" :: "r"(dst), "l"(src));
}
__device__ __forceinline__ char q8(float f, float clamp, float scale) {
    return (char)__float2int_rn(fminf(fmaxf(f, -clamp), clamp) * scale);
}

// ---------------------------------------------------------------------------
// K0: h[b] = mean of context embeddings; fp32 copy + int8 quantized copy
// ---------------------------------------------------------------------------
__global__ void k_h(const int* __restrict__ x, const float* __restrict__ emb_v) {
    int b = blockIdx.x;
    int t = threadIdx.x;  // 128 threads
    __shared__ int ctx[CTX];
    if (t < CTX) ctx[t] = x[b * CTX + t];
    __syncthreads();
    if (t == 0) g_negsum[b] = 0.0f;
    float s = 0.0f;
    if (t < EMB) {
#pragma unroll
        for (int c = 0; c < CTX; c++) s += emb_v[(size_t)ctx[c] * EMB + t];
        s *= 0.1f;
        g_h[b * EMB + t] = s;
    }
    g_hq[b * KP + t] = (t < EMB) ? q8(s, 1.6f, QH) : (char)0;
}

// ---------------------------------------------------------------------------
// K1: emb_u -> int8 quantized, padded [VP][KP]
// ---------------------------------------------------------------------------
__global__ void k_u(const float* __restrict__ emb_u) {
    int i = blockIdx.x * blockDim.x + threadIdx.x;  // 4-byte word index
    if (i >= VP * KP / 4) return;
    int v = i >> 5, w = i & 31;
    char4 out = {0, 0, 0, 0};
    if (v < VOCAB) {
        int k = w * 4;
        const float* row = emb_u + (size_t)v * EMB;
        if (k + 0 < EMB) out.x = q8(row[k + 0], 5.5f, QU);
        if (k + 1 < EMB) out.y = q8(row[k + 1], 5.5f, QU);
        if (k + 2 < EMB) out.z = q8(row[k + 2], 5.5f, QU);
        if (k + 3 < EMB) out.w = q8(row[k + 3], 5.5f, QU);
    }
    ((char4*)g_uq)[i] = out;
}

// ---------------------------------------------------------------------------
// K2: int8 GEMM (scores = h @ U^T) fused with sigmoid-sum over vocab.
//     CTA: M=128 batch rows (A pinned in smem), streams 14 B tiles (128 vocab
//     rows each) through a cp.async double buffer.
//     8 warps = 4(M) x 2(N); warp tile 32x64; mma.sync m16n8k32 s8 -> s32.
// ---------------------------------------------------------------------------
__global__ void __launch_bounds__(256) k_gemm() {
    extern __shared__ __align__(16) char smem[];
    uint32_t sbase = s2u(smem);
    int t = threadIdx.x, w = t >> 5, lane = t & 31;
    int g = lane >> 2, tig = lane & 3;
    int arow0 = (w >> 1) * 32;     // warp M slice
    int brow0 = (w & 1) * 64;      // warp N slice
    int mbase = blockIdx.y * BM;
    int tile0 = blockIdx.x * TPC;

    // Load A tile (128 rows x 128B) into smem[0..ABYTES)
    const uint4* gA = (const uint4*)(g_hq + (size_t)mbase * KP);
#pragma unroll
    for (int i = 0; i < 4; i++) {
        int idx = t + i * 256;          // 1024 16B chunks
        int r = idx >> 3, c = idx & 7;
        *(uint4*)(smem + r * STR + c * 16) = gA[idx];
    }

    // Prime B tile 0 into buffer 0
    {
        const char* gB = g_uq + (size_t)tile0 * BN * KP;
        uint32_t sb = sbase + ABYTES;
#pragma unroll
        for (int i = 0; i < 4; i++) {
            int idx = t + i * 256;
            int r = idx >> 3, c = idx & 7;
            cpa16(sb + r * STR + c * 16, gB + idx * 16);
        }
        asm volatile("cp.async.commit_group;" ::: "memory");
    }

    float rs[4] = {0.0f, 0.0f, 0.0f, 0.0f};

    for (int j = 0; j < TPC; j++) {
        asm volatile("cp.async.wait_group 0;" ::: "memory");
        __syncthreads();
        if (j + 1 < TPC) {
            const char* gB = g_uq + (size_t)(tile0 + j + 1) * BN * KP;
            uint32_t sb = sbase + ABYTES + ((j + 1) & 1) * ABYTES;
#pragma unroll
            for (int i = 0; i < 4; i++) {
                int idx = t + i * 256;
                int r = idx >> 3, c = idx & 7;
                cpa16(sb + r * STR + c * 16, gB + idx * 16);
            }
            asm volatile("cp.async.commit_group;" ::: "memory");
        }

        const char* sA = smem;
        const char* sB = smem + ABYTES + (j & 1) * ABYTES;

        int acc[2][8][4];
#pragma unroll
        for (int im = 0; im < 2; im++)
#pragma unroll
            for (int in = 0; in < 8; in++)
#pragma unroll
                for (int q = 0; q < 4; q++) acc[im][in][q] = 0;

#pragma unroll
        for (int ks = 0; ks < 4; ks++) {
            int k0 = ks * 32;
            uint32_t a[2][4], b[8][2];
#pragma unroll
            for (int im = 0; im < 2; im++) {
                int r0 = arow0 + im * 16 + g;
                a[im][0] = *(const uint32_t*)(sA + (r0    ) * STR + k0      + 4 * tig);
                a[im][1] = *(const uint32_t*)(sA + (r0 + 8) * STR + k0      + 4 * tig);
                a[im][2] = *(const uint32_t*)(sA + (r0    ) * STR + k0 + 16 + 4 * tig);
                a[im][3] = *(const uint32_t*)(sA + (r0 + 8) * STR + k0 + 16 + 4 * tig);
            }
#pragma unroll
            for (int in = 0; in < 8; in++) {
                int rn = brow0 + in * 8 + g;
                b[in][0] = *(const uint32_t*)(sB + rn * STR + k0      + 4 * tig);
                b[in][1] = *(const uint32_t*)(sB + rn * STR + k0 + 16 + 4 * tig);
            }
#pragma unroll
            for (int im = 0; im < 2; im++)
#pragma unroll
                for (int in = 0; in < 8; in++)
                    asm volatile(
                        "mma.sync.aligned.m16n8k32.row.col.s32.s8.s8.s32 "
                        "{%0,%1,%2,%3}, {%4,%5,%6,%7}, {%8,%9}, {%0,%1,%2,%3};"
                        : "+r"(acc[im][in][0]), "+r"(acc[im][in][1]),
                          "+r"(acc[im][in][2]), "+r"(acc[im][in][3])
                        : "r"(a[im][0]), "r"(a[im][1]), "r"(a[im][2]), "r"(a[im][3]),
                          "r"(b[in][0]), "r"(b[in][1]));
        }

        // Epilogue: sigmoid(-score) = 0.5 - 0.5*tanh(score/2), mask pad columns
        int nbase = (tile0 + j) * BN;
#pragma unroll
        for (int im = 0; im < 2; im++)
#pragma unroll
            for (int in = 0; in < 8; in++)
#pragma unroll
                for (int q = 0; q < 4; q++) {
                    int n = nbase + brow0 + in * 8 + 2 * tig + (q & 1);
                    if (n < VOCAB) {
                        float sc = (float)acc[im][in][q] * SCALE;
                        rs[im * 2 + (q >> 1)] += 0.5f - 0.5f * tanh_approx(0.5f * sc);
                    }
                }
    }

    // Reduce the 4 column-lanes sharing each row, then one atomic per row
#pragma unroll
    for (int i = 0; i < 4; i++) {
        rs[i] += __shfl_xor_sync(0xffffffff, rs[i], 1);
        rs[i] += __shfl_xor_sync(0xffffffff, rs[i], 2);
    }
    if (tig == 0) {
#pragma unroll
        for (int im = 0; im < 2; im++)
#pragma unroll
            for (int h = 0; h < 2; h++) {
                int row = mbase + arow0 + im * 16 + h * 8 + g;
                atomicAdd(&g_negsum[row], rs[im * 2 + h]);
            }
    }
}

// ---------------------------------------------------------------------------
// K3: per-b: pos = -log_sigmoid(dot(emb_u[y], h)); perb = pos + log(negsum)
// ---------------------------------------------------------------------------
__global__ void k_perb(const int* __restrict__ y, const float* __restrict__ emb_u) {
    int gwarp = (blockIdx.x * blockDim.x + threadIdx.x) >> 5;
    int lane = threadIdx.x & 31;
    if (gwarp >= BATCH) return;
    int b = gwarp;
    const float* u = emb_u + (size_t)y[b] * EMB;
    const float* h = g_h + (size_t)b * EMB;
    float d = 0.0f;
    for (int e = lane; e < EMB; e += 32) d += u[e] * h[e];
#pragma unroll
    for (int o = 16; o; o >>= 1) d += __shfl_xor_sync(0xffffffff, d, o);
    if (lane == 0) {
        float ls = (d >= 0.0f) ? -log1pf(expf(-d)) : d - log1pf(expf(d));
        g_perb[b] = -ls + logf(g_negsum[b]);
    }
}

// ---------------------------------------------------------------------------
// K4: deterministic mean reduction -> scalar out
// ---------------------------------------------------------------------------
__global__ void k_final(float* __restrict__ out) {
    __shared__ float s[256];
    int t = threadIdx.x;
    float v = 0.0f;
    for (int i = t; i < BATCH; i += 256) v += g_perb[i];
    s[t] = v;
    __syncthreads();
    for (int o = 128; o; o >>= 1) {
        if (t < o) s[t] += s[t + o];
        __syncthreads();
    }
    if (t == 0) out[0] = s[0] / (float)BATCH;
}

// ---------------------------------------------------------------------------
extern "C" void kernel_launch(void* const* d_in, const int* in_sizes, int n_in,
                              void* d_out, int out_size) {
    const int*   x     = (const int*)d_in[0];
    const int*   y     = (const int*)d_in[1];
    const float* emb_v = (const float*)d_in[2];
    const float* emb_u = (const float*)d_in[3];

    cudaFuncSetAttribute(k_gemm, cudaFuncAttributeMaxDynamicSharedMemorySize, SMEM_TOTAL);

    k_h<<<BATCH, 128>>>(x, emb_v);
    k_u<<<(VP * KP / 4 + 255) / 256, 256>>>(emb_u);
    dim3 grid(NSPLIT, BATCH / BM);  // 28 x 16
    k_gemm<<<grid, 256, SMEM_TOTAL>>>();
    k_perb<<<BATCH / 8, 256>>>(y, emb_u);
    k_final<<<1, 256>>>((float*)d_out);
}

// round 5
// speedup vs baseline: 2.1314x; 2.1314x over previous
#include <cuda_runtime.h>
#include <cuda_bf16.h>
#include <cstdint>

#define BATCH 2048
#define VOCAB 50000
#define EMB   100
#define CTX   10
#define KP    112          // K padded to 112 (7 x k16 mma steps)
#define VP    50176        // 784 * 64
#define BM    128
#define BN    64
#define NSPLIT 56
#define TPC    14          // B tiles per CTA = 784/56
#define STRB   240         // smem row stride bytes (224B data + pad, conflict-free)
#define ABYTES (BM * STRB) // 30720
#define BBYTES (BN * STRB) // 15360
#define SMEM_TOTAL (ABYTES + 2 * BBYTES)  // 61440

// Scratch (device globals)
__device__ float                           g_h[BATCH * EMB];
__device__ __align__(16) __nv_bfloat16     g_hb[BATCH * KP];
__device__ __align__(16) __nv_bfloat16     g_ub[VP * KP];   // emb_u * 0.5, bf16
__device__ float                           g_negsum[BATCH]; // accumulates sum of tanh
__device__ float                           g_perb[BATCH];

__device__ __forceinline__ uint32_t s2u(const void* p) {
    uint32_t a;
    asm("{ .reg .u64 t; cvta.to.shared.u64 t, %1; cvt.u32.u64 %0, t; }" : "=r"(a) : "l"(p));
    return a;
}
__device__ __forceinline__ float tanh_approx(float x) {
    float y;
    asm("tanh.approx.f32 %0, %1;" : "=f"(y) : "f"(x));
    return y;
}
__device__ __forceinline__ void cpa16(uint32_t dst, const void* src) {
    asm volatile("cp.async.cg.shared.global [%0], [%1], 16;" :: "r"(dst), "l"(src));
}

// ---------------------------------------------------------------------------
// K0: h[b] = mean of context embeddings; fp32 copy + bf16 padded copy; zero negsum
// ---------------------------------------------------------------------------
__global__ void k_h(const int* __restrict__ x, const float* __restrict__ emb_v) {
    int b = blockIdx.x;
    int t = threadIdx.x;  // 128 threads
    __shared__ int ctx[CTX];
    if (t < CTX) ctx[t] = x[b * CTX + t];
    __syncthreads();
    if (t == 0) g_negsum[b] = 0.0f;
    float s = 0.0f;
    if (t < EMB) {
#pragma unroll
        for (int c = 0; c < CTX; c++) s += emb_v[(size_t)ctx[c] * EMB + t];
        s *= 0.1f;
        g_h[b * EMB + t] = s;
    }
    if (t < KP) g_hb[b * KP + t] = __float2bfloat16(t < EMB ? s : 0.0f);
}

// ---------------------------------------------------------------------------
// K1: emb_u * 0.5 -> bf16, padded [VP][KP] (zeros in pad region)
// ---------------------------------------------------------------------------
__global__ void k_u(const float* __restrict__ emb_u) {
    int i = blockIdx.x * blockDim.x + threadIdx.x;
    if (i >= VP * KP) return;
    int v = i / KP, k = i % KP;
    float val = (v < VOCAB && k < EMB) ? 0.5f * emb_u[v * EMB + k] : 0.0f;
    g_ub[i] = __float2bfloat16(val);
}

// ---------------------------------------------------------------------------
// K2: bf16 GEMM (acc = (h @ U^T)/2, via pre-scaled U) fused with tanh-sum.
//     CTA: M=128 batch rows (A pinned in smem), streams 14 B tiles (64 vocab
//     rows each) through a cp.async double buffer.
//     8 warps = 4(M) x 2(N); warp tile 32x32; mma.sync m16n8k16 bf16 -> f32.
//     Epilogue floor: per score exactly MUFU.TANH + FADD (no mask, no scale).
// ---------------------------------------------------------------------------
__global__ void __launch_bounds__(256) k_gemm() {
    extern __shared__ __align__(16) char smem[];
    uint32_t sbase = s2u(smem);
    int t = threadIdx.x, w = t >> 5, lane = t & 31;
    int g = lane >> 2, tig = lane & 3;
    int arow0 = (w >> 1) * 32;     // warp M slice
    int brow0 = (w & 1) * 32;      // warp N slice
    int mbase = blockIdx.y * BM;
    int tile0 = blockIdx.x * TPC;

    // Load A tile (128 rows x 224B) into smem[0..ABYTES)
    const uint4* gA = (const uint4*)(g_hb + (size_t)mbase * KP);
#pragma unroll
    for (int i = 0; i < 7; i++) {
        int idx = t + i * 256;          // 1792 16B chunks
        int r = idx / 14, c = idx % 14;
        *(uint4*)(smem + r * STRB + c * 16) = gA[idx];
    }

    // Prime B tile 0 into buffer 0
    {
        const char* gB = (const char*)(g_ub + (size_t)tile0 * BN * KP);
        uint32_t sb = sbase + ABYTES;
#pragma unroll
        for (int i = 0; i < 4; i++) {
            int idx = t + i * 256;      // 896 chunks
            if (idx < BN * 14) {
                int r = idx / 14, c = idx % 14;
                cpa16(sb + r * STRB + c * 16, gB + idx * 16);
            }
        }
        asm volatile("cp.async.commit_group;" ::: "memory");
    }

    float rs[4] = {0.0f, 0.0f, 0.0f, 0.0f};   // per-(im,rowhalf) tanh sums

    for (int j = 0; j < TPC; j++) {
        asm volatile("cp.async.wait_group 0;" ::: "memory");
        __syncthreads();
        if (j + 1 < TPC) {
            const char* gB = (const char*)(g_ub + (size_t)(tile0 + j + 1) * BN * KP);
            uint32_t sb = sbase + ABYTES + ((j + 1) & 1) * BBYTES;
#pragma unroll
            for (int i = 0; i < 4; i++) {
                int idx = t + i * 256;
                if (idx < BN * 14) {
                    int r = idx / 14, c = idx % 14;
                    cpa16(sb + r * STRB + c * 16, gB + idx * 16);
                }
            }
            asm volatile("cp.async.commit_group;" ::: "memory");
        }

        const char* sA = smem;
        const char* sB = smem + ABYTES + (j & 1) * BBYTES;

        float acc[2][4][4];
#pragma unroll
        for (int im = 0; im < 2; im++)
#pragma unroll
            for (int in = 0; in < 4; in++)
#pragma unroll
                for (int q = 0; q < 4; q++) acc[im][in][q] = 0.0f;

#pragma unroll
        for (int ks = 0; ks < 7; ks++) {
            int kb = ks * 32;               // byte offset (16 bf16 per step)
            uint32_t a[2][4], b[4][2];
#pragma unroll
            for (int im = 0; im < 2; im++) {
                int r0 = arow0 + im * 16 + g;
                a[im][0] = *(const uint32_t*)(sA + (r0    ) * STRB + kb      + 4 * tig);
                a[im][1] = *(const uint32_t*)(sA + (r0 + 8) * STRB + kb      + 4 * tig);
                a[im][2] = *(const uint32_t*)(sA + (r0    ) * STRB + kb + 16 + 4 * tig);
                a[im][3] = *(const uint32_t*)(sA + (r0 + 8) * STRB + kb + 16 + 4 * tig);
            }
#pragma unroll
            for (int in = 0; in < 4; in++) {
                int rn = brow0 + in * 8 + g;
                b[in][0] = *(const uint32_t*)(sB + rn * STRB + kb      + 4 * tig);
                b[in][1] = *(const uint32_t*)(sB + rn * STRB + kb + 16 + 4 * tig);
            }
#pragma unroll
            for (int im = 0; im < 2; im++)
#pragma unroll
                for (int in = 0; in < 4; in++)
                    asm volatile(
                        "mma.sync.aligned.m16n8k16.row.col.f32.bf16.bf16.f32 "
                        "{%0,%1,%2,%3}, {%4,%5,%6,%7}, {%8,%9}, {%0,%1,%2,%3};"
                        : "+f"(acc[im][in][0]), "+f"(acc[im][in][1]),
                          "+f"(acc[im][in][2]), "+f"(acc[im][in][3])
                        : "r"(a[im][0]), "r"(a[im][1]), "r"(a[im][2]), "r"(a[im][3]),
                          "r"(b[in][0]), "r"(b[in][1]));
        }

        // Epilogue: acc already = score/2; sum tanh only (pads give exact 0)
#pragma unroll
        for (int im = 0; im < 2; im++)
#pragma unroll
            for (int in = 0; in < 4; in++)
#pragma unroll
                for (int q = 0; q < 4; q++)
                    rs[im * 2 + (q >> 1)] += tanh_approx(acc[im][in][q]);
    }

    // Reduce the 4 column-lanes sharing each row, then one atomic per row
#pragma unroll
    for (int i = 0; i < 4; i++) {
        rs[i] += __shfl_xor_sync(0xffffffff, rs[i], 1);
        rs[i] += __shfl_xor_sync(0xffffffff, rs[i], 2);
    }
    if (tig == 0) {
#pragma unroll
        for (int im = 0; im < 2; im++)
#pragma unroll
            for (int h = 0; h < 2; h++) {
                int row = mbase + arow0 + im * 16 + h * 8 + g;
                atomicAdd(&g_negsum[row], rs[im * 2 + h]);
            }
    }
}

// ---------------------------------------------------------------------------
// K3: per-b: pos = -log_sigmoid(dot(emb_u[y], h));
//     neg = log( sum sigmoid(-s) ) = log( 0.5*VOCAB - 0.5*sum(tanh(s/2)) )
// ---------------------------------------------------------------------------
__global__ void k_perb(const int* __restrict__ y, const float* __restrict__ emb_u) {
    int gwarp = (blockIdx.x * blockDim.x + threadIdx.x) >> 5;
    int lane = threadIdx.x & 31;
    if (gwarp >= BATCH) return;
    int b = gwarp;
    const float* u = emb_u + (size_t)y[b] * EMB;
    const float* h = g_h + (size_t)b * EMB;
    float d = 0.0f;
    for (int e = lane; e < EMB; e += 32) d += u[e] * h[e];
#pragma unroll
    for (int o = 16; o; o >>= 1) d += __shfl_xor_sync(0xffffffff, d, o);
    if (lane == 0) {
        float ls = (d >= 0.0f) ? -log1pf(expf(-d)) : d - log1pf(expf(d));
        g_perb[b] = -ls + logf(0.5f * (float)VOCAB - 0.5f * g_negsum[b]);
    }
}

// ---------------------------------------------------------------------------
// K4: deterministic mean reduction -> scalar out
// ---------------------------------------------------------------------------
__global__ void k_final(float* __restrict__ out) {
    __shared__ float s[256];
    int t = threadIdx.x;
    float v = 0.0f;
    for (int i = t; i < BATCH; i += 256) v += g_perb[i];
    s[t] = v;
    __syncthreads();
    for (int o = 128; o; o >>= 1) {
        if (t < o) s[t] += s[t + o];
        __syncthreads();
    }
    if (t == 0) out[0] = s[0] / (float)BATCH;
}

// ---------------------------------------------------------------------------
extern "C" void kernel_launch(void* const* d_in, const int* in_sizes, int n_in,
                              void* d_out, int out_size) {
    const int*   x     = (const int*)d_in[0];
    const int*   y     = (const int*)d_in[1];
    const float* emb_v = (const float*)d_in[2];
    const float* emb_u = (const float*)d_in[3];

    cudaFuncSetAttribute(k_gemm, cudaFuncAttributeMaxDynamicSharedMemorySize, SMEM_TOTAL);

    k_h<<<BATCH, 128>>>(x, emb_v);
    k_u<<<(VP * KP + 255) / 256, 256>>>(emb_u);
    dim3 grid(NSPLIT, BATCH / BM);  // 56 x 16
    k_gemm<<<grid, 256, SMEM_TOTAL>>>();
    k_perb<<<BATCH / 8, 256>>>(y, emb_u);
    k_final<<<1, 256>>>((float*)d_out);
}

// round 6
// speedup vs baseline: 2.2740x; 1.0669x over previous
#include <cuda_runtime.h>
#include <cuda_bf16.h>
#include <cstdint>

#define BATCH 2048
#define VOCAB 50000
#define EMB   100
#define CTX   10
#define KP    112          // K padded to 112 (7 x k16 mma steps)
#define VP    50176        // 392 * 128
#define BM    128
#define BN    128
#define NSPLIT 56
#define TPC    7           // B tiles per CTA = 392/56
#define STRB   240         // smem row stride bytes (224B data + 16 pad)
#define ABYTES (BM * STRB) // 30720
#define BBYTES (BN * STRB) // 30720
#define SMEM_TOTAL (ABYTES + 2 * BBYTES)  // 92160

// Scratch (device globals)
__device__ float                           g_h[BATCH * EMB];
__device__ __align__(16) __nv_bfloat16     g_hb[BATCH * KP];
__device__ __align__(16) __nv_bfloat16     g_ub[VP * KP];   // emb_u * 0.5, bf16
__device__ float                           g_negsum[BATCH]; // sum of tanh(score/2)
__device__ float                           g_perb[BATCH];

__device__ __forceinline__ uint32_t s2u(const void* p) {
    uint32_t a;
    asm("{ .reg .u64 t; cvta.to.shared.u64 t, %1; cvt.u32.u64 %0, t; }" : "=r"(a) : "l"(p));
    return a;
}
__device__ __forceinline__ float tanh_approx(float x) {
    float y;
    asm("tanh.approx.f32 %0, %1;" : "=f"(y) : "f"(x));
    return y;
}
__device__ __forceinline__ void cpa16(uint32_t dst, const void* src) {
    asm volatile("cp.async.cg.shared.global [%0], [%1], 16;" :: "r"(dst), "l"(src));
}
__device__ __forceinline__ void ldsm4(uint32_t& r0, uint32_t& r1, uint32_t& r2,
                                      uint32_t& r3, uint32_t addr) {
    asm volatile("ldmatrix.sync.aligned.m8n8.x4.shared.b16 {%0,%1,%2,%3}, [%4];"
                 : "=r"(r0), "=r"(r1), "=r"(r2), "=r"(r3) : "r"(addr));
}

// ---------------------------------------------------------------------------
// K0: h[b] = mean of context embeddings; fp32 copy + bf16 padded copy; zero negsum
// ---------------------------------------------------------------------------
__global__ void k_h(const int* __restrict__ x, const float* __restrict__ emb_v) {
    int b = blockIdx.x;
    int t = threadIdx.x;  // 128 threads
    __shared__ int ctx[CTX];
    if (t < CTX) ctx[t] = x[b * CTX + t];
    __syncthreads();
    if (t == 0) g_negsum[b] = 0.0f;
    float s = 0.0f;
    if (t < EMB) {
#pragma unroll
        for (int c = 0; c < CTX; c++) s += emb_v[(size_t)ctx[c] * EMB + t];
        s *= 0.1f;
        g_h[b * EMB + t] = s;
    }
    if (t < KP) g_hb[b * KP + t] = __float2bfloat16(t < EMB ? s : 0.0f);
}

// ---------------------------------------------------------------------------
// K1: emb_u * 0.5 -> bf16, padded [VP][KP] (zeros in pad region)
// ---------------------------------------------------------------------------
__global__ void k_u(const float* __restrict__ emb_u) {
    int i = blockIdx.x * blockDim.x + threadIdx.x;
    if (i >= VP * KP) return;
    int v = i / KP, k = i % KP;
    float val = (v < VOCAB && k < EMB) ? 0.5f * emb_u[v * EMB + k] : 0.0f;
    g_ub[i] = __float2bfloat16(val);
}

// ---------------------------------------------------------------------------
// K2: bf16 GEMM (acc = (h @ U^T)/2 via pre-scaled U) fused with tanh-sum.
//     CTA: M=128 batch rows pinned in smem; streams 7 B tiles (128 vocab rows)
//     through a cp.async double buffer.
//     8 warps = 4(M) x 2(N); warp tile 32x64; ldmatrix.x4 fragment loads;
//     mma.sync m16n8k16 bf16 -> f32. Epilogue: MUFU.TANH + FADD per score.
// ---------------------------------------------------------------------------
__global__ void __launch_bounds__(256, 2) k_gemm() {
    extern __shared__ __align__(16) char smem[];
    uint32_t sbase = s2u(smem);
    int t = threadIdx.x, w = t >> 5, lane = t & 31;
    int g = lane >> 2, tig = lane & 3;
    int arow0 = (w >> 1) * 32;     // warp M slice
    int brow0 = (w & 1) * 64;      // warp N slice
    int mbase = blockIdx.y * BM;
    int tile0 = blockIdx.x * TPC;

    // ldmatrix per-lane address components (byte offsets within a tile)
    // A: t0-15 -> rows 0-15 @kb, t16-31 -> rows 0-15 @kb+16
    uint32_t aoff0 = sbase + (arow0 + (lane & 15)) * STRB + (lane >> 4) * 16;
    // B: t0-7 rows0-7@kb, t8-15 rows0-7@kb+16, t16-23 rows8-15@kb, t24-31 rows8-15@kb+16
    uint32_t boff0 = (brow0 + ((lane >> 4) << 3) + (lane & 7)) * STRB
                   + ((lane >> 3) & 1) * 16;

    // Load A tile (128 rows x 224B)
    const uint4* gA = (const uint4*)(g_hb + (size_t)mbase * KP);
#pragma unroll
    for (int i = 0; i < 7; i++) {
        int idx = t + i * 256;          // 1792 16B chunks
        int r = idx / 14, c = idx % 14;
        *(uint4*)(smem + r * STRB + c * 16) = gA[idx];
    }

    // Prime B tile 0 into buffer 0
    {
        const char* gB = (const char*)(g_ub + (size_t)tile0 * BN * KP);
        uint32_t sb = sbase + ABYTES;
#pragma unroll
        for (int i = 0; i < 7; i++) {
            int idx = t + i * 256;
            int r = idx / 14, c = idx % 14;
            cpa16(sb + r * STRB + c * 16, gB + idx * 16);
        }
        asm volatile("cp.async.commit_group;" ::: "memory");
    }

    float rs[4] = {0.0f, 0.0f, 0.0f, 0.0f};

    for (int j = 0; j < TPC; j++) {
        asm volatile("cp.async.wait_group 0;" ::: "memory");
        __syncthreads();
        if (j + 1 < TPC) {
            const char* gB = (const char*)(g_ub + (size_t)(tile0 + j + 1) * BN * KP);
            uint32_t sb = sbase + ABYTES + ((j + 1) & 1) * BBYTES;
#pragma unroll
            for (int i = 0; i < 7; i++) {
                int idx = t + i * 256;
                int r = idx / 14, c = idx % 14;
                cpa16(sb + r * STRB + c * 16, gB + idx * 16);
            }
            asm volatile("cp.async.commit_group;" ::: "memory");
        }

        uint32_t bbuf = sbase + ABYTES + (j & 1) * BBYTES + boff0;

        float acc[2][8][4];
#pragma unroll
        for (int im = 0; im < 2; im++)
#pragma unroll
            for (int in = 0; in < 8; in++)
#pragma unroll
                for (int q = 0; q < 4; q++) acc[im][in][q] = 0.0f;

#pragma unroll
        for (int ks = 0; ks < 7; ks++) {
            int kb = ks * 32;               // byte offset (16 bf16)
            uint32_t a[2][4], b[8][2];
#pragma unroll
            for (int im = 0; im < 2; im++)
                ldsm4(a[im][0], a[im][1], a[im][2], a[im][3],
                      aoff0 + im * 16 * STRB + kb);
#pragma unroll
            for (int jn = 0; jn < 4; jn++)
                ldsm4(b[2 * jn][0], b[2 * jn][1], b[2 * jn + 1][0], b[2 * jn + 1][1],
                      bbuf + jn * 16 * STRB + kb);
#pragma unroll
            for (int im = 0; im < 2; im++)
#pragma unroll
                for (int in = 0; in < 8; in++)
                    asm volatile(
                        "mma.sync.aligned.m16n8k16.row.col.f32.bf16.bf16.f32 "
                        "{%0,%1,%2,%3}, {%4,%5,%6,%7}, {%8,%9}, {%0,%1,%2,%3};"
                        : "+f"(acc[im][in][0]), "+f"(acc[im][in][1]),
                          "+f"(acc[im][in][2]), "+f"(acc[im][in][3])
                        : "r"(a[im][0]), "r"(a[im][1]), "r"(a[im][2]), "r"(a[im][3]),
                          "r"(b[in][0]), "r"(b[in][1]));
        }

        // Epilogue: acc already = score/2; sum tanh only (pads give exact 0)
#pragma unroll
        for (int im = 0; im < 2; im++)
#pragma unroll
            for (int in = 0; in < 8; in++)
#pragma unroll
                for (int q = 0; q < 4; q++)
                    rs[im * 2 + (q >> 1)] += tanh_approx(acc[im][in][q]);
    }

    // Reduce the 4 column-lanes sharing each row, then one atomic per row
#pragma unroll
    for (int i = 0; i < 4; i++) {
        rs[i] += __shfl_xor_sync(0xffffffff, rs[i], 1);
        rs[i] += __shfl_xor_sync(0xffffffff, rs[i], 2);
    }
    if (tig == 0) {
#pragma unroll
        for (int im = 0; im < 2; im++)
#pragma unroll
            for (int h = 0; h < 2; h++) {
                int row = mbase + arow0 + im * 16 + h * 8 + g;
                atomicAdd(&g_negsum[row], rs[im * 2 + h]);
            }
    }
}

// ---------------------------------------------------------------------------
// K3: per-b: pos = -log_sigmoid(dot(emb_u[y], h));
//     neg = log( 0.5*VOCAB - 0.5*sum_tanh )
// ---------------------------------------------------------------------------
__global__ void k_perb(const int* __restrict__ y, const float* __restrict__ emb_u) {
    int gwarp = (blockIdx.x * blockDim.x + threadIdx.x) >> 5;
    int lane = threadIdx.x & 31;
    if (gwarp >= BATCH) return;
    int b = gwarp;
    const float* u = emb_u + (size_t)y[b] * EMB;
    const float* h = g_h + (size_t)b * EMB;
    float d = 0.0f;
    for (int e = lane; e < EMB; e += 32) d += u[e] * h[e];
#pragma unroll
    for (int o = 16; o; o >>= 1) d += __shfl_xor_sync(0xffffffff, d, o);
    if (lane == 0) {
        float ls = (d >= 0.0f) ? -log1pf(expf(-d)) : d - log1pf(expf(d));
        g_perb[b] = -ls + logf(0.5f * (float)VOCAB - 0.5f * g_negsum[b]);
    }
}

// ---------------------------------------------------------------------------
// K4: deterministic mean reduction -> scalar out
// ---------------------------------------------------------------------------
__global__ void k_final(float* __restrict__ out) {
    __shared__ float s[256];
    int t = threadIdx.x;
    float v = 0.0f;
    for (int i = t; i < BATCH; i += 256) v += g_perb[i];
    s[t] = v;
    __syncthreads();
    for (int o = 128; o; o >>= 1) {
        if (t < o) s[t] += s[t + o];
        __syncthreads();
    }
    if (t == 0) out[0] = s[0] / (float)BATCH;
}

// ---------------------------------------------------------------------------
extern "C" void kernel_launch(void* const* d_in, const int* in_sizes, int n_in,
                              void* d_out, int out_size) {
    const int*   x     = (const int*)d_in[0];
    const int*   y     = (const int*)d_in[1];
    const float* emb_v = (const float*)d_in[2];
    const float* emb_u = (const float*)d_in[3];

    cudaFuncSetAttribute(k_gemm, cudaFuncAttributeMaxDynamicSharedMemorySize, SMEM_TOTAL);

    k_h<<<BATCH, 128>>>(x, emb_v);
    k_u<<<(VP * KP + 255) / 256, 256>>>(emb_u);
    dim3 grid(NSPLIT, BATCH / BM);  // 56 x 16
    k_gemm<<<grid, 256, SMEM_TOTAL>>>();
    k_perb<<<BATCH / 8, 256>>>(y, emb_u);
    k_final<<<1, 256>>>((float*)d_out);
}